// round 12
// baseline (speedup 1.0000x reference)
#include <cuda_runtime.h>
#include <cuda_fp16.h>
#include <cstdint>
#include <math_constants.h>

#define B_SZ  2
#define S_LEN 2048
#define D_EMB 1024
#define NH    16
#define HD    64

// Scratch (allocation-free rule: __device__ globals)
__device__ __half g_xh  [B_SZ * S_LEN * D_EMB];      // x in fp16
__device__ __half g_wqh [3 * D_EMB * D_EMB];         // w_qkv in fp16
__device__ __half g_woh [D_EMB * D_EMB];             // w_out in fp16
__device__ __half g_qkvh[B_SZ * S_LEN * 3 * D_EMB];  // qkv fp16
__device__ __half g_atth[B_SZ * S_LEN * D_EMB];      // attention out fp16

// ---------------------------------------------------------------------------
// Helpers
// ---------------------------------------------------------------------------
__device__ __forceinline__ uint32_t smem_to_u32(const void* p) {
    uint32_t a;
    asm("{ .reg .u64 t; cvta.to.shared.u64 t, %1; cvt.u32.u64 %0, t; }"
        : "=r"(a) : "l"(p));
    return a;
}
__device__ __forceinline__ void cp_async16(uint32_t dst, const void* src) {
    asm volatile("cp.async.cg.shared.global [%0], [%1], 16;"
                 :: "r"(dst), "l"(src) : "memory");
}
__device__ __forceinline__ void cp_async_commit() {
    asm volatile("cp.async.commit_group;" ::: "memory");
}
__device__ __forceinline__ uint32_t packh2(float lo, float hi) {
    uint32_t r;
    asm("cvt.rn.f16x2.f32 %0, %2, %1;" : "=r"(r) : "f"(lo), "f"(hi));
    return r;
}
__device__ __forceinline__ uint32_t ex2_h2(uint32_t x) {
    uint32_t r;
    asm("ex2.approx.f16x2 %0, %1;" : "=r"(r) : "r"(x));
    return r;
}

#define LDSM_X4(R, addr) \
    asm volatile("ldmatrix.sync.aligned.m8n8.x4.shared.b16 {%0,%1,%2,%3}, [%4];" \
        : "=r"((R)[0]), "=r"((R)[1]), "=r"((R)[2]), "=r"((R)[3]) : "r"(addr))

#define LDSM_X4_T(R, addr) \
    asm volatile("ldmatrix.sync.aligned.m8n8.x4.trans.shared.b16 {%0,%1,%2,%3}, [%4];" \
        : "=r"((R)[0]), "=r"((R)[1]), "=r"((R)[2]), "=r"((R)[3]) : "r"(addr))

#define MMA_F16(C, A, B0, B1) \
    asm volatile("mma.sync.aligned.m16n8k16.row.col.f32.f16.f16.f32 " \
        "{%0,%1,%2,%3}, {%4,%5,%6,%7}, {%8,%9}, {%0,%1,%2,%3};" \
        : "+f"((C)[0]), "+f"((C)[1]), "+f"((C)[2]), "+f"((C)[3]) \
        : "r"((A)[0]), "r"((A)[1]), "r"((A)[2]), "r"((A)[3]), "r"(B0), "r"(B1))

// ---------------------------------------------------------------------------
// fp32 -> fp16 conversion pre-pass
// ---------------------------------------------------------------------------
__global__ void to_half_kernel(const float4* __restrict__ src,
                               __half2* __restrict__ dst, int n4)
{
    int i = blockIdx.x * blockDim.x + threadIdx.x;
    if (i < n4) {
        float4 v = src[i];
        dst[2 * i]     = __floats2half2_rn(v.x, v.y);
        dst[2 * i + 1] = __floats2half2_rn(v.z, v.w);
    }
}

// ---------------------------------------------------------------------------
// fp16 mma.sync GEMM (unchanged, known-good)
// ---------------------------------------------------------------------------
#define GEMM_DSMEM (1024 + 3 * 32768)

template<int HALF_OUT>
__global__ __launch_bounds__(256) void gemm_f16(
    const __half* __restrict__ A, const __half* __restrict__ B,
    void* __restrict__ Cv, int N, int K)
{
    extern __shared__ char dyn[];
    const uint32_t tile = (smem_to_u32(dyn) + 1023u) & ~1023u;
    const int tid  = threadIdx.x;
    const int lane = tid & 31;
    const int warp = tid >> 5;
    const int wm = warp & 3;
    const int wn = warp >> 2;
    const int bm = blockIdx.y * 128;
    const int bn = blockIdx.x * 128;
    const int tl = lane >> 3;

    const int r0 = tid >> 1;
    const int c0 = (tid & 1) * 4;
    uint32_t dsw[4];
#pragma unroll
    for (int j = 0; j < 4; j++) {
        uint32_t off = (uint32_t)r0 * 128u + (uint32_t)(c0 + j) * 16u;
        dsw[j] = off ^ ((off >> 3) & 0x70u);
    }
    const __half* Ab = A + (long)bm * K;
    const __half* Bb = B + (long)bn * K;

#define ISSUE(kc, s) do {                                                   \
        uint32_t sa_ = tile + (uint32_t)(s) * 32768u;                       \
        uint32_t sb_ = sa_ + 16384u;                                        \
        const __half* pA = Ab + (long)r0 * K + (kc) * 64;                   \
        const __half* pB = Bb + (long)r0 * K + (kc) * 64;                   \
        _Pragma("unroll")                                                   \
        for (int j = 0; j < 4; j++) {                                       \
            cp_async16(sa_ + dsw[j], pA + (c0 + j) * 8);                    \
            cp_async16(sb_ + dsw[j], pB + (c0 + j) * 8);                    \
        }                                                                   \
        cp_async_commit();                                                  \
    } while (0)

    const int mrow = wm * 32 + (tl & 1) * 8 + (lane & 7);
    const uint32_t a_base = (uint32_t)mrow * 128u + (uint32_t)(tl >> 1) * 16u;
    const uint32_t a_xm   = (uint32_t)(mrow & 7) << 4;
    const int nrow = wn * 64 + (tl >> 1) * 8 + (lane & 7);
    const uint32_t b_base = (uint32_t)nrow * 128u + (uint32_t)(tl & 1) * 16u;
    const uint32_t b_xm   = (uint32_t)(nrow & 7) << 4;

    float acc[2][8][4];
#pragma unroll
    for (int mt = 0; mt < 2; mt++)
#pragma unroll
        for (int j = 0; j < 8; j++)
#pragma unroll
            for (int q = 0; q < 4; q++) acc[mt][j][q] = 0.0f;

    const int NC = K / 64;
    ISSUE(0, 0);
    ISSUE(1, 1);

#pragma unroll 1
    for (int kc = 0; kc < NC; kc++) {
        if (kc == NC - 1) asm volatile("cp.async.wait_group 0;" ::: "memory");
        else              asm volatile("cp.async.wait_group 1;" ::: "memory");
        __syncthreads();
        if (kc + 2 < NC) ISSUE(kc + 2, (kc + 2) % 3);

        const uint32_t sa = tile + (uint32_t)(kc % 3) * 32768u;
        const uint32_t sb = sa + 16384u;

#pragma unroll
        for (int ks = 0; ks < 4; ks++) {
            uint32_t a[2][4], b[4][4];
#pragma unroll
            for (int mt = 0; mt < 2; mt++)
                LDSM_X4(a[mt], sa + ((a_base + (uint32_t)mt * 2048u + (uint32_t)ks * 32u) ^ a_xm));
#pragma unroll
            for (int nt = 0; nt < 4; nt++)
                LDSM_X4(b[nt], sb + ((b_base + (uint32_t)nt * 2048u + (uint32_t)ks * 32u) ^ b_xm));
#pragma unroll
            for (int mt = 0; mt < 2; mt++)
#pragma unroll
                for (int nt = 0; nt < 4; nt++) {
                    MMA_F16(acc[mt][2 * nt],     a[mt], b[nt][0], b[nt][1]);
                    MMA_F16(acc[mt][2 * nt + 1], a[mt], b[nt][2], b[nt][3]);
                }
        }
    }

    const int lr = lane >> 2;
    const int lcx = lane & 3;
#pragma unroll
    for (int mt = 0; mt < 2; mt++) {
#pragma unroll
        for (int j = 0; j < 8; j++) {
            const long row = bm + wm * 32 + mt * 16 + lr;
            const long col = bn + wn * 64 + j * 8 + lcx * 2;
            if (HALF_OUT) {
                __half* C = (__half*)Cv;
                *(__half2*)(C + row * N + col) =
                    __floats2half2_rn(acc[mt][j][0], acc[mt][j][1]);
                *(__half2*)(C + (row + 8) * N + col) =
                    __floats2half2_rn(acc[mt][j][2], acc[mt][j][3]);
            } else {
                float* C = (float*)Cv;
                *(float2*)(C + row * N + col) =
                    make_float2(acc[mt][j][0], acc[mt][j][1]);
                *(float2*)(C + (row + 8) * N + col) =
                    make_float2(acc[mt][j][2], acc[mt][j][3]);
            }
        }
    }
#undef ISSUE
}

// ---------------------------------------------------------------------------
// fp16 flash attention, kv-split warps.
// One CTA per (b, h, 128-q tile). 8 warps = 4 q-groups (32 rows) x 2 kv
// halves (64 rows). Each warp reads only its kv-half of K/V (smem reads
// halved vs 16x128 tiles); partial O/l merged once at the end via smem.
// Static-shift softmax, register P, l via ones-column MMA. 3-stage KV.
// Smem: KV stages (K+V 32KB) @0/32K/64K, Q @96K, ones @112K, partials @114K.
// ---------------------------------------------------------------------------
#define CH 128
#define NT (S_LEN / CH)
#define Q_OFF    98304u
#define ONES_OFF 114688u
#define PART_OFF 116736u
#define ATTN_DSMEM (1024 + 116736 + 4 * 9216)
#define QSCALE 0.1803368801111f   /* 0.125 * log2(e) */
#define SHIFT  8.0f               /* static softmax shift (cancels in out) */

__global__ __launch_bounds__(256) void attn_f16(
    const __half* __restrict__ qkvh, __half* __restrict__ atth)
{
    extern __shared__ char dyn[];
    char* dynb = (char*)(((uintptr_t)dyn + 1023) & ~(uintptr_t)1023);
    const uint32_t base = smem_to_u32(dynb);
    const uint32_t Qa = base + Q_OFF;
    const uint32_t OnesA = base + ONES_OFF;
    char* onesb = dynb + ONES_OFF;

    const int tid = threadIdx.x, lane = tid & 31, warp = tid >> 5;
    const int qt = blockIdx.x, h = blockIdx.y, b = blockIdx.z;
    const int gr = lane >> 2, lc = lane & 3, tl = lane >> 3;
    const int qg = warp >> 1;         // q group: 32 rows
    const int kh = warp & 1;          // kv half: 64 rows

    const __half* qg_p = qkvh + ((long)b * S_LEN + (long)qt * 128) * 3072 + h * HD;
    const __half* kgh  = qkvh + (long)b * S_LEN * 3072 + D_EMB + h * HD;
    const __half* vgh  = kgh + D_EMB;

    const int r0 = tid >> 1;
    const int c0 = (tid & 1) * 4;
    uint32_t dsw[4];
#pragma unroll
    for (int j = 0; j < 4; j++) {
        uint32_t off = (uint32_t)r0 * 128u + (uint32_t)(c0 + j) * 16u;
        dsw[j] = off ^ ((off >> 3) & 0x70u);
    }

#define KV_ISSUE(c, s) do {                                                  \
        const __half* ks_ = kgh + (long)((c) * CH + r0) * 3072;              \
        const __half* vs_ = vgh + (long)((c) * CH + r0) * 3072;              \
        uint32_t kd_ = base + (uint32_t)(s) * 32768u;                        \
        uint32_t vd_ = kd_ + 16384u;                                         \
        _Pragma("unroll")                                                    \
        for (int j = 0; j < 4; j++) cp_async16(kd_ + dsw[j], ks_ + (c0 + j) * 8); \
        _Pragma("unroll")                                                    \
        for (int j = 0; j < 4; j++) cp_async16(vd_ + dsw[j], vs_ + (c0 + j) * 8); \
        cp_async_commit();                                                   \
    } while (0)

    // ---- ones tile zero (2KB), then prologue loads
    ((float2*)onesb)[tid] = make_float2(0.0f, 0.0f);

    {   // Q (commit group 0)
        const __half* qs = qg_p + (long)r0 * 3072;
#pragma unroll
        for (int j = 0; j < 4; j++) cp_async16(Qa + dsw[j], qs + (c0 + j) * 8);
        cp_async_commit();
    }
    KV_ISSUE(0, 0);
    KV_ISSUE(1, 1);
    KV_ISSUE(2, 2);

    if (tid < 16)
        *(uint16_t*)(onesb + tid * 128 + ((tid & 7) << 4)) = 0x3C00;  // 1.0h

    asm volatile("cp.async.wait_group 3;" ::: "memory");   // Q done
    __syncthreads();                                       // Q + ones visible

    // ---- Q fragments: 2 m16 tiles x 4 k16 steps
    uint32_t qa[2][4][4];
#pragma unroll
    for (int mt = 0; mt < 2; mt++) {
        const uint32_t arow = (uint32_t)(qg * 32 + mt * 16 + (tl & 1) * 8 + (lane & 7));
        const uint32_t a_xm = (arow & 7u) << 4;
#pragma unroll
        for (int ks = 0; ks < 4; ks++)
            LDSM_X4(qa[mt][ks], Qa + ((arow * 128u + (uint32_t)ks * 32u + (uint32_t)(tl >> 1) * 16u) ^ a_xm));
    }

    // per-lane smem address pieces (within this warp's kv half)
    const uint32_t krow  = (uint32_t)(kh * 64 + (tl >> 1) * 8 + (lane & 7));
    const uint32_t k_off = krow * 128u + (uint32_t)(tl & 1) * 16u;
    const uint32_t k_xm  = (krow & 7u) << 4;
    const uint32_t vrow  = (uint32_t)(kh * 64 + (lane & 7) + (lane & 8));
    const uint32_t v_off = vrow * 128u + (uint32_t)((lane >> 4) & 1) * 16u;
    const uint32_t v_xm  = (vrow & 7u) << 4;
    const uint32_t orow  = (uint32_t)((lane & 7) + (lane & 8));
    const uint32_t o_off = orow * 128u + (uint32_t)((lane >> 4) & 1) * 16u;
    const uint32_t o_xm  = (orow & 7u) << 4;

    // ---- ones B-fragment (constant)
    uint32_t of[4];
    LDSM_X4_T(of, OnesA + (o_off ^ o_xm));

    float oacc[2][8][4];
#pragma unroll
    for (int mt = 0; mt < 2; mt++)
#pragma unroll
        for (int j = 0; j < 8; j++)
#pragma unroll
            for (int q = 0; q < 4; q++) oacc[mt][j][q] = 0.0f;
    float lacc[2][4] = {{0, 0, 0, 0}, {0, 0, 0, 0}};

#pragma unroll 1
    for (int kt = 0; kt < NT; kt++) {
        const int s = kt % 3;
        const uint32_t Kba = base + (uint32_t)s * 32768u;
        const uint32_t Vba = Kba + 16384u;

        if (kt == NT - 1)      asm volatile("cp.async.wait_group 0;" ::: "memory");
        else if (kt == NT - 2) asm volatile("cp.async.wait_group 1;" ::: "memory");
        else                   asm volatile("cp.async.wait_group 2;" ::: "memory");
        __syncthreads();   // KV[kt] visible

        // ---- S = Q K^T  (2 m16 x 8 kv8-tiles x 4 k16-steps, kv-half only)
        float sacc[2][8][4];
#pragma unroll
        for (int mt = 0; mt < 2; mt++)
#pragma unroll
            for (int j = 0; j < 8; j++)
#pragma unroll
                for (int q = 0; q < 4; q++) sacc[mt][j][q] = 0.0f;

#pragma unroll
        for (int ks = 0; ks < 4; ks++) {
#pragma unroll
            for (int g = 0; g < 4; g++) {
                uint32_t kb[4];
                LDSM_X4(kb, Kba + ((k_off + (uint32_t)g * 2048u + (uint32_t)ks * 32u) ^ k_xm));
                MMA_F16(sacc[0][2 * g],     qa[0][ks], kb[0], kb[1]);
                MMA_F16(sacc[0][2 * g + 1], qa[0][ks], kb[2], kb[3]);
                MMA_F16(sacc[1][2 * g],     qa[1][ks], kb[0], kb[1]);
                MMA_F16(sacc[1][2 * g + 1], qa[1][ks], kb[2], kb[3]);
            }
        }

        // ---- static-shift softmax: p = 2^(s*QSCALE - SHIFT), fp16x2 exp
        uint32_t pb[2][4][4];
#pragma unroll
        for (int mt = 0; mt < 2; mt++)
#pragma unroll
            for (int j = 0; j < 4; j++) {
                pb[mt][j][0] = ex2_h2(packh2(fmaf(sacc[mt][2 * j][0],     QSCALE, -SHIFT),
                                             fmaf(sacc[mt][2 * j][1],     QSCALE, -SHIFT)));
                pb[mt][j][1] = ex2_h2(packh2(fmaf(sacc[mt][2 * j][2],     QSCALE, -SHIFT),
                                             fmaf(sacc[mt][2 * j][3],     QSCALE, -SHIFT)));
                pb[mt][j][2] = ex2_h2(packh2(fmaf(sacc[mt][2 * j + 1][0], QSCALE, -SHIFT),
                                             fmaf(sacc[mt][2 * j + 1][1], QSCALE, -SHIFT)));
                pb[mt][j][3] = ex2_h2(packh2(fmaf(sacc[mt][2 * j + 1][2], QSCALE, -SHIFT),
                                             fmaf(sacc[mt][2 * j + 1][3], QSCALE, -SHIFT)));
            }

        // ---- O += P V ; l += P 1   (4 k16-steps over kv-half x 4 d16)
#pragma unroll
        for (int ks2 = 0; ks2 < 4; ks2++) {
#pragma unroll
            for (int dt = 0; dt < 4; dt++) {
                uint32_t vb[4];
                LDSM_X4_T(vb, Vba + ((v_off + (uint32_t)ks2 * 2048u + (uint32_t)dt * 32u) ^ v_xm));
                MMA_F16(oacc[0][2 * dt],     pb[0][ks2], vb[0], vb[1]);
                MMA_F16(oacc[0][2 * dt + 1], pb[0][ks2], vb[2], vb[3]);
                MMA_F16(oacc[1][2 * dt],     pb[1][ks2], vb[0], vb[1]);
                MMA_F16(oacc[1][2 * dt + 1], pb[1][ks2], vb[2], vb[3]);
            }
            MMA_F16(lacc[0], pb[0][ks2], of[0], of[1]);
            MMA_F16(lacc[1], pb[1][ks2], of[0], of[1]);
        }
        __syncthreads();   // all warps done reading KV[s]

        if (kt + 3 < NT) KV_ISSUE(kt + 3, s);
    }

    // ---- combine kv-halves: kh==1 stores partial O/l; kh==0 adds + writes
    float* pr = (float*)(dynb + PART_OFF + qg * 9216);
    if (kh == 1) {
#pragma unroll
        for (int mt = 0; mt < 2; mt++)
#pragma unroll
            for (int nt = 0; nt < 8; nt++)
                *(float4*)(pr + ((mt * 8 + nt) * 32 + lane) * 4) =
                    make_float4(oacc[mt][nt][0], oacc[mt][nt][1],
                                oacc[mt][nt][2], oacc[mt][nt][3]);
#pragma unroll
        for (int mt = 0; mt < 2; mt++)
            *(float4*)(pr + 2048 + (mt * 32 + lane) * 4) =
                make_float4(lacc[mt][0], lacc[mt][1], lacc[mt][2], lacc[mt][3]);
    }
    __syncthreads();
    if (kh == 0) {
#pragma unroll
        for (int mt = 0; mt < 2; mt++) {
#pragma unroll
            for (int nt = 0; nt < 8; nt++) {
                float4 v = *(float4*)(pr + ((mt * 8 + nt) * 32 + lane) * 4);
                oacc[mt][nt][0] += v.x; oacc[mt][nt][1] += v.y;
                oacc[mt][nt][2] += v.z; oacc[mt][nt][3] += v.w;
            }
            float4 lv = *(float4*)(pr + 2048 + (mt * 32 + lane) * 4);
            lacc[mt][0] += lv.x; lacc[mt][2] += lv.z;

            const float l0 = __shfl_sync(0xffffffffu, lacc[mt][0], lane & ~3);
            const float l1 = __shfl_sync(0xffffffffu, lacc[mt][2], lane & ~3);
            const float inv0 = 1.0f / l0;
            const float inv1 = 1.0f / l1;
            __half* og = atth + ((long)b * S_LEN + (long)qt * 128 + qg * 32 + mt * 16 + gr) * D_EMB
                       + h * HD + 2 * lc;
#pragma unroll
            for (int nt = 0; nt < 8; nt++) {
                *(__half2*)(og + nt * 8) =
                    __floats2half2_rn(oacc[mt][nt][0] * inv0, oacc[mt][nt][1] * inv0);
                *(__half2*)(og + 8 * D_EMB + nt * 8) =
                    __floats2half2_rn(oacc[mt][nt][2] * inv1, oacc[mt][nt][3] * inv1);
            }
        }
    }
#undef KV_ISSUE
}

// ---------------------------------------------------------------------------
extern "C" void kernel_launch(void* const* d_in, const int* in_sizes, int n_in,
                              void* d_out, int out_size)
{
    const float* x     = (const float*)d_in[0];   // [2,2048,1024]
    const float* w_qkv = (const float*)d_in[1];   // [3072,1024]
    const float* w_out = (const float*)d_in[2];   // [1024,1024]
    float* out = (float*)d_out;                   // [2,2048,1024]

    __half *xh, *wqh, *woh, *qkvh, *atth;
    cudaGetSymbolAddress((void**)&xh,   g_xh);
    cudaGetSymbolAddress((void**)&wqh,  g_wqh);
    cudaGetSymbolAddress((void**)&woh,  g_woh);
    cudaGetSymbolAddress((void**)&qkvh, g_qkvh);
    cudaGetSymbolAddress((void**)&atth, g_atth);

    const int M = B_SZ * S_LEN;      // 4096

    cudaFuncSetAttribute(gemm_f16<1>, cudaFuncAttributeMaxDynamicSharedMemorySize, GEMM_DSMEM);
    cudaFuncSetAttribute(gemm_f16<0>, cudaFuncAttributeMaxDynamicSharedMemorySize, GEMM_DSMEM);
    cudaFuncSetAttribute(attn_f16, cudaFuncAttributeMaxDynamicSharedMemorySize, ATTN_DSMEM);

    // 0) fp32 -> fp16 pre-pass
    {
        int n4x = M * D_EMB / 4;
        int n4q = 3 * D_EMB * D_EMB / 4;
        int n4o = D_EMB * D_EMB / 4;
        to_half_kernel<<<(n4x + 255) / 256, 256>>>((const float4*)x, (__half2*)xh, n4x);
        to_half_kernel<<<(n4q + 255) / 256, 256>>>((const float4*)w_qkv, (__half2*)wqh, n4q);
        to_half_kernel<<<(n4o + 255) / 256, 256>>>((const float4*)w_out, (__half2*)woh, n4o);
    }

    // 1) QKV projection (fp16 out)
    gemm_f16<1><<<dim3(3 * D_EMB / 128, M / 128), 256, GEMM_DSMEM>>>(xh, wqh, qkvh, 3 * D_EMB, D_EMB);

    // 2) Attention (fp16 in/out, kv-split warps, register P)
    attn_f16<<<dim3(S_LEN / 128, NH, B_SZ), 256, ATTN_DSMEM>>>(qkvh, atth);

    // 3) Output projection (fp32 out)
    gemm_f16<0><<<dim3(D_EMB / 128, M / 128), 256, GEMM_DSMEM>>>(atth, woh, out, D_EMB, D_EMB);
}